// round 5
// baseline (speedup 1.0000x reference)
#include <cuda_runtime.h>
#include <cstdint>

#define NN        8192
#define KSEL      64
#define NTHREADS  256
#define CAP       768
#define THRESH    2.0f
#define TBITS     0x40000000u   // float bits of 2.0f

__device__ __forceinline__ uint64_t make_key(uint32_t bits, uint32_t idx) {
    // larger key == larger value; ties -> smaller index (top_k order)
    return ((uint64_t)bits << 16) | (uint64_t)(0xFFFFu ^ idx);
}

// Warp-aggregated histogram add (fallback path only).
__device__ __forceinline__ void hist_add(uint32_t* hist, uint32_t bin, bool pred, int lane) {
    unsigned act = __ballot_sync(0xffffffffu, pred);
    if (pred) {
        unsigned same   = __match_any_sync(act, bin);
        int      leader = __ffs(same) - 1;
        if (lane == leader) atomicAdd(&hist[bin], (uint32_t)__popc(same));
    }
}

__global__ __launch_bounds__(NTHREADS)
void topk_mask_kernel(const float* __restrict__ A, float* __restrict__ out)
{
    __shared__ uint64_t cand[CAP];
    __shared__ uint32_t cand_count;
    __shared__ uint32_t hist[256];
    __shared__ uint32_t wsum[8];
    __shared__ uint32_t sh_b, sh_kp, sh_deg;

    const int    tid  = threadIdx.x;
    const int    lane = tid & 31;
    const size_t row  = blockIdx.x;

    const float*  arowf = A + row * (size_t)NN;
    const float4* arow  = reinterpret_cast<const float4*>(arowf);
    float4*       orow  = reinterpret_cast<float4*>(out + row * (size_t)NN);

    if (tid == 0) cand_count = 0;
    hist[tid] = 0;
    __syncthreads();

    const float4 z4 = make_float4(0.0f, 0.0f, 0.0f, 0.0f);

    // ---- Single sweep: read A, zero-fill out, push candidates (v >= THRESH) ----
    // Hot path per float4: LDG.128 + STG.128 + 3 FMNMX + 1 FSETP + branch.
    // cand[] order is irrelevant (selection is by key), so no ballot/scan logic.
    #pragma unroll
    for (int i = tid; i < NN / 4; i += NTHREADS) {
        float4 v = arow[i];
        orow[i] = z4;                               // independent: pure BW
        const float vmax = fmaxf(fmaxf(v.x, v.y), fmaxf(v.z, v.w));
        if (vmax >= THRESH) {
            uint32_t m = 0;
            m |= (v.x >= THRESH) ? 1u : 0u;
            m |= (v.y >= THRESH) ? 2u : 0u;
            m |= (v.z >= THRESH) ? 4u : 0u;
            m |= (v.w >= THRESH) ? 8u : 0u;
            uint32_t off = atomicAdd(&cand_count, (uint32_t)__popc(m));
            if (m & 1u) { if (off < CAP) cand[off] = make_key(__float_as_uint(v.x), 4u * i + 0u); off++; }
            if (m & 2u) { if (off < CAP) cand[off] = make_key(__float_as_uint(v.y), 4u * i + 1u); off++; }
            if (m & 4u) { if (off < CAP) cand[off] = make_key(__float_as_uint(v.z), 4u * i + 2u); off++; }
            if (m & 8u) { if (off < CAP) cand[off] = make_key(__float_as_uint(v.w), 4u * i + 3u); off++; }
        }
    }
    __syncthreads();

    const uint32_t C = cand_count;
    if (C >= KSEL && C <= CAP) {
        // Fast path valid: the 64th-largest is >= THRESH, so cand[] holds the
        // entire top-64. O(C) bucket select on a monotone 8-bit refinement key.
        for (uint32_t j = tid; j < C; j += NTHREADS) {
            const uint32_t bits = (uint32_t)(cand[j] >> 16);
            const uint32_t bin  = umin(255u, (bits - TBITS) >> 16);
            atomicAdd(&hist[bin], 1u);              // C adds total, sparse bins
        }
        __syncthreads();

        {   // suffix scan over 256 bins -> crossing bucket b, in-bucket rank kp
            const uint32_t v0 = hist[tid];
            uint32_t v = v0;
            #pragma unroll
            for (int d = 1; d < 32; d <<= 1) {
                uint32_t o = __shfl_down_sync(0xffffffffu, v, d);
                if (lane + d < 32) v += o;
            }
            if (lane == 0) wsum[tid >> 5] = v;
            __syncthreads();
            uint32_t hi = 0;
            #pragma unroll
            for (int w = 0; w < 8; ++w) if (w > (tid >> 5)) hi += wsum[w];
            const uint32_t s   = v + hi;    // count of candidates with bin >= tid
            const uint32_t nxt = s - v0;    // count with bin > tid
            if (s >= KSEL && nxt < KSEL) { sh_b = (uint32_t)tid; sh_kp = KSEL - nxt; }
            __syncthreads();
        }
        const uint32_t b  = sh_b;
        const uint32_t kp = sh_kp;

        // Winners: bin > b unconditionally; bin == b ranked exactly (few ties).
        for (uint32_t j = tid; j < C; j += NTHREADS) {
            const uint64_t kj   = cand[j];
            const uint32_t bits = (uint32_t)(kj >> 16);
            const uint32_t bin  = umin(255u, (bits - TBITS) >> 16);
            if (bin > b) {
                const uint32_t idx = 0xFFFFu ^ (uint32_t)(kj & 0xFFFFu);
                out[row * (size_t)NN + idx] = __uint_as_float(bits);
            } else if (bin == b) {
                uint32_t r = 0;
                for (uint32_t mm = 0; mm < C; ++mm) {
                    const uint64_t km = cand[mm];
                    const uint32_t bm = umin(255u, ((uint32_t)(km >> 16) - TBITS) >> 16);
                    r += (bm == b && km > kj) ? 1u : 0u;
                }
                if (r < kp) {
                    const uint32_t idx = 0xFFFFu ^ (uint32_t)(kj & 0xFFFFu);
                    out[row * (size_t)NN + idx] = __uint_as_float(bits);
                }
            }
        }
        return;
    }

    // ================= Exact fallback (bracket failed; never taken on N(0,1)) =========
    hist[tid] = 0;
    if (tid == 0) { sh_b = 0; sh_kp = 0; sh_deg = 0; cand_count = 0; }
    __syncthreads();

    for (int i = tid; i < NN / 4; i += NTHREADS) {
        float4 v = arow[i];
        uint32_t b0 = (v.x > 0.0f) ? __float_as_uint(v.x) : 0u;
        uint32_t b1 = (v.y > 0.0f) ? __float_as_uint(v.y) : 0u;
        uint32_t b2 = (v.z > 0.0f) ? __float_as_uint(v.z) : 0u;
        uint32_t b3 = (v.w > 0.0f) ? __float_as_uint(v.w) : 0u;
        hist_add(hist, b0 >> 24, b0 != 0u, lane);
        hist_add(hist, b1 >> 24, b1 != 0u, lane);
        hist_add(hist, b2 >> 24, b2 != 0u, lane);
        hist_add(hist, b3 >> 24, b3 != 0u, lane);
    }
    __syncthreads();

    {   // suffix scan over 256 byte bins
        const uint32_t v0 = hist[tid];
        uint32_t v = v0;
        #pragma unroll
        for (int d = 1; d < 32; d <<= 1) {
            uint32_t o = __shfl_down_sync(0xffffffffu, v, d);
            if (lane + d < 32) v += o;
        }
        if (lane == 0) wsum[tid >> 5] = v;
        __syncthreads();
        uint32_t hi = 0;
        #pragma unroll
        for (int w = 0; w < 8; ++w) if (w > (tid >> 5)) hi += wsum[w];
        const uint32_t s   = v + hi;     // count with top byte >= tid
        const uint32_t nxt = s - v0;     // count with top byte  > tid
        if (tid == 0 && s < KSEL) sh_deg = 1;
        if (s >= KSEL && nxt < KSEL) { sh_b = (uint32_t)tid; sh_kp = KSEL - nxt; }
        __syncthreads();
    }
    const uint32_t b   = sh_b;
    const uint32_t kp  = sh_kp;
    const bool     deg = (sh_deg != 0);

    // zeros are already in place from the first sweep; write survivors only
    for (int i = tid; i < NN; i += NTHREADS) {
        const float    v    = arowf[i];
        const uint32_t bits = (v > 0.0f) ? __float_as_uint(v) : 0u;
        if (deg) {
            if (bits) out[row * (size_t)NN + i] = v;   // <K positives: keep all
        } else if (bits) {
            const uint32_t byte = bits >> 24;
            if (byte > b) out[row * (size_t)NN + i] = v;
            else if (byte == b) {
                const uint32_t p = atomicAdd(&cand_count, 1u);
                if (p < CAP) cand[p] = make_key(bits, (uint32_t)i);
            }
        }
    }
    __syncthreads();

    if (!deg) {
        const uint32_t C2 = cand_count;
        if (C2 <= CAP) {
            for (uint32_t j = tid; j < C2; j += NTHREADS) {
                const uint64_t kj = cand[j];
                uint32_t r = 0;
                for (uint32_t mm = 0; mm < C2; ++mm)
                    r += (cand[mm] > kj) ? 1u : 0u;
                if (r < kp) {
                    const uint32_t idx = 0xFFFFu ^ (uint32_t)(kj & 0xFFFFu);
                    out[row * (size_t)NN + idx] = __uint_as_float((uint32_t)(kj >> 16));
                }
            }
        } else {
            // ultra-rare duplicate-heavy rows: O(N) exact rank per candidate
            for (int i = tid; i < NN; i += NTHREADS) {
                const float    v    = arowf[i];
                const uint32_t bits = (v > 0.0f) ? __float_as_uint(v) : 0u;
                if (bits && (bits >> 24) == b) {
                    const uint64_t kj = make_key(bits, (uint32_t)i);
                    uint32_t r = 0;
                    for (int j2 = 0; j2 < NN; ++j2) {
                        const float    w  = arowf[j2];
                        const uint32_t wb = (w > 0.0f) ? __float_as_uint(w) : 0u;
                        if (wb && (wb >> 24) == b && make_key(wb, (uint32_t)j2) > kj) ++r;
                    }
                    if (r < kp) out[row * (size_t)NN + i] = v;
                }
            }
        }
    }
}

extern "C" void kernel_launch(void* const* d_in, const int* in_sizes, int n_in,
                              void* d_out, int out_size) {
    const float* A   = (const float*)d_in[0];
    float*       out = (float*)d_out;
    (void)in_sizes; (void)n_in; (void)out_size;   // idx (d_in[1]) unused by the reference
    topk_mask_kernel<<<NN, NTHREADS>>>(A, out);
}

// round 6
// speedup vs baseline: 1.2799x; 1.2799x over previous
#include <cuda_runtime.h>
#include <cstdint>

#define NN        8192
#define KSEL      64
#define NTHREADS  256
#define WCAP      128            // per-warp candidate slots (8 warps -> 1024 total)
#define THRESH    2.15f

__device__ __forceinline__ uint64_t make_key(uint32_t bits, uint32_t idx) {
    // larger key == larger value; ties -> smaller index (top_k order)
    return ((uint64_t)bits << 16) | (uint64_t)(0xFFFFu ^ idx);
}

// Warp-aggregated histogram add (fallback path only).
__device__ __forceinline__ void hist_add(uint32_t* hist, uint32_t bin, bool pred, int lane) {
    unsigned act = __ballot_sync(0xffffffffu, pred);
    if (pred) {
        unsigned same   = __match_any_sync(act, bin);
        int      leader = __ffs(same) - 1;
        if (lane == leader) atomicAdd(&hist[bin], (uint32_t)__popc(same));
    }
}

__global__ __launch_bounds__(NTHREADS)
void topk_mask_kernel(const float* __restrict__ A, float* __restrict__ out)
{
    __shared__ uint64_t cand[8 * WCAP];     // per-warp segments
    __shared__ uint32_t cnt_s[8];
    __shared__ uint32_t hist[256];          // fallback only
    __shared__ uint32_t wsum[8];
    __shared__ uint32_t fb_count;
    __shared__ uint32_t sh_b, sh_kp, sh_deg;

    const int    tid  = threadIdx.x;
    const int    lane = tid & 31;
    const int    warp = tid >> 5;
    const size_t row  = blockIdx.x;

    const float*  arowf = A + row * (size_t)NN;
    const float4* arow  = reinterpret_cast<const float4*>(arowf);
    float4*       orow  = reinterpret_cast<float4*>(out + row * (size_t)NN);

    uint64_t* myseg = cand + (warp << 7);
    const unsigned ltm = (1u << lane) - 1u;

    const float4 z4 = make_float4(0.0f, 0.0f, 0.0f, 0.0f);
    uint32_t base = 0;   // per-warp candidate count, uniform across lanes (no atomics)

    // ---- Single sweep: batched loads (MLP=4), zero stores, ballot-compacted push ----
    #pragma unroll
    for (int it = 0; it < 2; ++it) {
        const int i0 = it * 1024 + tid;       // float4 index, stride NTHREADS
        float4 v[4];
        #pragma unroll
        for (int u = 0; u < 4; ++u) v[u] = arow[i0 + u * NTHREADS];
        #pragma unroll
        for (int u = 0; u < 4; ++u) orow[i0 + u * NTHREADS] = z4;
        #pragma unroll
        for (int u = 0; u < 4; ++u) {
            const uint32_t eb = (uint32_t)(i0 + u * NTHREADS) * 4u;
            unsigned a;
            a = __ballot_sync(0xffffffffu, v[u].x >= THRESH);
            if (v[u].x >= THRESH) { uint32_t o = base + __popc(a & ltm); if (o < WCAP) myseg[o] = make_key(__float_as_uint(v[u].x), eb + 0u); }
            base += (uint32_t)__popc(a);
            a = __ballot_sync(0xffffffffu, v[u].y >= THRESH);
            if (v[u].y >= THRESH) { uint32_t o = base + __popc(a & ltm); if (o < WCAP) myseg[o] = make_key(__float_as_uint(v[u].y), eb + 1u); }
            base += (uint32_t)__popc(a);
            a = __ballot_sync(0xffffffffu, v[u].z >= THRESH);
            if (v[u].z >= THRESH) { uint32_t o = base + __popc(a & ltm); if (o < WCAP) myseg[o] = make_key(__float_as_uint(v[u].z), eb + 2u); }
            base += (uint32_t)__popc(a);
            a = __ballot_sync(0xffffffffu, v[u].w >= THRESH);
            if (v[u].w >= THRESH) { uint32_t o = base + __popc(a & ltm); if (o < WCAP) myseg[o] = make_key(__float_as_uint(v[u].w), eb + 3u); }
            base += (uint32_t)__popc(a);
        }
    }
    if (lane == 0) cnt_s[warp] = base;
    __syncthreads();

    // Validity: every segment within cap, and total >= KSEL (then the KSEL-th
    // largest is >= THRESH, so the candidate set provably holds the top-KSEL).
    uint32_t C = 0; bool ok = true;
    #pragma unroll
    for (int w = 0; w < 8; ++w) { const uint32_t cw = cnt_s[w]; C += cw; ok &= (cw <= WCAP); }

    if (ok && C >= KSEL) {
        // ---- Exact rank (value desc, index asc) over segmented candidates ----
        for (int s = tid; s < 8 * WCAP; s += NTHREADS) {
            const int w = s >> 7, o = s & (WCAP - 1);
            if ((uint32_t)o < cnt_s[w]) {
                const uint64_t kj = cand[s];
                uint32_t r = 0;
                #pragma unroll
                for (int w2 = 0; w2 < 8; ++w2) {
                    const uint32_t  n2  = cnt_s[w2];
                    const uint64_t* seg = cand + (w2 << 7);
                    for (uint32_t m2 = 0; m2 < n2; ++m2)
                        r += (seg[m2] > kj) ? 1u : 0u;     // broadcast LDS
                }
                if (r < KSEL) {
                    const uint32_t idx = 0xFFFFu ^ (uint32_t)(kj & 0xFFFFu);
                    out[row * (size_t)NN + idx] = __uint_as_float((uint32_t)(kj >> 16));
                }
            }
        }
        return;
    }

    // ================= Exact fallback (bracket failed; never taken on N(0,1)) =========
    hist[tid] = 0;
    if (tid == 0) { sh_b = 0; sh_kp = 0; sh_deg = 0; fb_count = 0; }
    __syncthreads();

    for (int i = tid; i < NN / 4; i += NTHREADS) {
        float4 v = arow[i];
        uint32_t b0 = (v.x > 0.0f) ? __float_as_uint(v.x) : 0u;
        uint32_t b1 = (v.y > 0.0f) ? __float_as_uint(v.y) : 0u;
        uint32_t b2 = (v.z > 0.0f) ? __float_as_uint(v.z) : 0u;
        uint32_t b3 = (v.w > 0.0f) ? __float_as_uint(v.w) : 0u;
        hist_add(hist, b0 >> 24, b0 != 0u, lane);
        hist_add(hist, b1 >> 24, b1 != 0u, lane);
        hist_add(hist, b2 >> 24, b2 != 0u, lane);
        hist_add(hist, b3 >> 24, b3 != 0u, lane);
    }
    __syncthreads();

    {   // suffix scan over 256 byte bins
        const uint32_t v0 = hist[tid];
        uint32_t v = v0;
        #pragma unroll
        for (int d = 1; d < 32; d <<= 1) {
            uint32_t o = __shfl_down_sync(0xffffffffu, v, d);
            if (lane + d < 32) v += o;
        }
        if (lane == 0) wsum[tid >> 5] = v;
        __syncthreads();
        uint32_t hi = 0;
        #pragma unroll
        for (int w = 0; w < 8; ++w) if (w > (tid >> 5)) hi += wsum[w];
        const uint32_t s   = v + hi;     // count with top byte >= tid
        const uint32_t nxt = s - v0;     // count with top byte  > tid
        if (tid == 0 && s < KSEL) sh_deg = 1;
        if (s >= KSEL && nxt < KSEL) { sh_b = (uint32_t)tid; sh_kp = KSEL - nxt; }
        __syncthreads();
    }
    const uint32_t b   = sh_b;
    const uint32_t kp  = sh_kp;
    const bool     deg = (sh_deg != 0);

    // zeros are already in place from the sweep; write survivors only
    for (int i = tid; i < NN; i += NTHREADS) {
        const float    v    = arowf[i];
        const uint32_t bits = (v > 0.0f) ? __float_as_uint(v) : 0u;
        if (deg) {
            if (bits) out[row * (size_t)NN + i] = v;   // <K positives: keep all
        } else if (bits) {
            const uint32_t byte = bits >> 24;
            if (byte > b) out[row * (size_t)NN + i] = v;
            else if (byte == b) {
                const uint32_t p = atomicAdd(&fb_count, 1u);
                if (p < 8 * WCAP) cand[p] = make_key(bits, (uint32_t)i);
            }
        }
    }
    __syncthreads();

    if (!deg) {
        const uint32_t C2 = fb_count;
        if (C2 <= 8 * WCAP) {
            for (uint32_t j = tid; j < C2; j += NTHREADS) {
                const uint64_t kj = cand[j];
                uint32_t r = 0;
                for (uint32_t mm = 0; mm < C2; ++mm)
                    r += (cand[mm] > kj) ? 1u : 0u;
                if (r < kp) {
                    const uint32_t idx = 0xFFFFu ^ (uint32_t)(kj & 0xFFFFu);
                    out[row * (size_t)NN + idx] = __uint_as_float((uint32_t)(kj >> 16));
                }
            }
        } else {
            // ultra-rare duplicate-heavy rows: O(N) exact rank per candidate
            for (int i = tid; i < NN; i += NTHREADS) {
                const float    v    = arowf[i];
                const uint32_t bits = (v > 0.0f) ? __float_as_uint(v) : 0u;
                if (bits && (bits >> 24) == b) {
                    const uint64_t kj = make_key(bits, (uint32_t)i);
                    uint32_t r = 0;
                    for (int j2 = 0; j2 < NN; ++j2) {
                        const float    w  = arowf[j2];
                        const uint32_t wb = (w > 0.0f) ? __float_as_uint(w) : 0u;
                        if (wb && (wb >> 24) == b && make_key(wb, (uint32_t)j2) > kj) ++r;
                    }
                    if (r < kp) out[row * (size_t)NN + i] = v;
                }
            }
        }
    }
}

extern "C" void kernel_launch(void* const* d_in, const int* in_sizes, int n_in,
                              void* d_out, int out_size) {
    const float* A   = (const float*)d_in[0];
    float*       out = (float*)d_out;
    (void)in_sizes; (void)n_in; (void)out_size;   // idx (d_in[1]) unused by the reference
    topk_mask_kernel<<<NN, NTHREADS>>>(A, out);
}